// round 1
// baseline (speedup 1.0000x reference)
#include <cuda_runtime.h>

// i1e(x) = exp(-|x|) * I1(x), A&S 9.8.3/9.8.4 rational approximations,
// matching the JAX reference's branch structure and Horner ordering.

__device__ __forceinline__ float i1e_scalar(float x) {
    float ax = fabsf(x);

    // ---- small branch: ax * P7((ax/3.75)^2) * exp(-ax) ----
    float ts = ax * (1.0f / 3.75f);
    ts = ts * ts;
    float ps = 0.00032411f;
    ps = fmaf(ps, ts, 0.00301532f);
    ps = fmaf(ps, ts, 0.02658733f);
    ps = fmaf(ps, ts, 0.15084934f);
    ps = fmaf(ps, ts, 0.51498869f);
    ps = fmaf(ps, ts, 0.87890594f);
    ps = fmaf(ps, ts, 0.5f);
    float small_v = ax * ps * __expf(-ax);

    // ---- large branch: P9(3.75/ax) / sqrt(ax) ----
    float axl = fmaxf(ax, 3.75f);
    float tl = __fdividef(3.75f, axl);
    float pl = -0.00420059f;
    pl = fmaf(pl, tl, 0.01787654f);
    pl = fmaf(pl, tl, -0.02895312f);
    pl = fmaf(pl, tl, 0.02282967f);
    pl = fmaf(pl, tl, -0.01031555f);
    pl = fmaf(pl, tl, 0.00163801f);
    pl = fmaf(pl, tl, -0.00362018f);
    pl = fmaf(pl, tl, -0.03988024f);
    pl = fmaf(pl, tl, 0.39894228f);
    float large_v = pl * rsqrtf(axl);

    float r = (ax <= 3.75f) ? small_v : large_v;
    return copysignf(r, x);   // I1 is odd; sign(0)*r == 0 matches since r==0 at x==0
}

__global__ void __launch_bounds__(256) i1e_vec4_kernel(
    const float4* __restrict__ in, float4* __restrict__ out, int n4) {
    int i = blockIdx.x * blockDim.x + threadIdx.x;
    if (i < n4) {
        float4 v = in[i];
        float4 r;
        r.x = i1e_scalar(v.x);
        r.y = i1e_scalar(v.y);
        r.z = i1e_scalar(v.z);
        r.w = i1e_scalar(v.w);
        out[i] = r;
    }
}

__global__ void i1e_tail_kernel(const float* __restrict__ in,
                                float* __restrict__ out, int start, int n) {
    int i = start + blockIdx.x * blockDim.x + threadIdx.x;
    if (i < n) out[i] = i1e_scalar(in[i]);
}

extern "C" void kernel_launch(void* const* d_in, const int* in_sizes, int n_in,
                              void* d_out, int out_size) {
    const float* z = (const float*)d_in[0];
    float* out = (float*)d_out;
    int n = in_sizes[0];
    int n4 = n >> 2;

    if (n4 > 0) {
        int threads = 256;
        int blocks = (n4 + threads - 1) / threads;
        i1e_vec4_kernel<<<blocks, threads>>>((const float4*)z, (float4*)out, n4);
    }
    int rem_start = n4 << 2;
    int rem = n - rem_start;
    if (rem > 0) {
        i1e_tail_kernel<<<1, 256>>>(z, out, rem_start, n);
    }
}

// round 2
// speedup vs baseline: 1.1858x; 1.1858x over previous
#include <cuda_runtime.h>
#include <cstdint>

// i1e(x) = exp(-|x|) * I1(x), A&S 9.8.3/9.8.4, matching the JAX reference.
// Two elements evaluated per packed f32x2 instruction (Blackwell FFMA2 path).

__device__ __forceinline__ uint64_t pk2(float a, float b) {
    uint64_t r;
    asm("mov.b64 %0, {%1, %2};" : "=l"(r) : "f"(a), "f"(b));
    return r;
}
__device__ __forceinline__ void upk2(uint64_t v, float& a, float& b) {
    asm("mov.b64 {%0, %1}, %2;" : "=f"(a), "=f"(b) : "l"(v));
}
__device__ __forceinline__ uint64_t bc2(float c) {
    uint32_t u = __float_as_uint(c);
    return ((uint64_t)u << 32) | (uint64_t)u;
}
__device__ __forceinline__ uint64_t fma2(uint64_t a, uint64_t b, uint64_t c) {
    uint64_t r;
    asm("fma.rn.f32x2 %0, %1, %2, %3;" : "=l"(r) : "l"(a), "l"(b), "l"(c));
    return r;
}
__device__ __forceinline__ uint64_t mul2(uint64_t a, uint64_t b) {
    uint64_t r;
    asm("mul.rn.f32x2 %0, %1, %2;" : "=l"(r) : "l"(a), "l"(b));
    return r;
}

// Evaluate i1e on a pair of floats.
__device__ __forceinline__ void i1e_pair(float x0, float x1, float& o0, float& o1) {
    float ax0 = fabsf(x0), ax1 = fabsf(x1);

    // MUFU work issued early (long latency, overlaps the packed Horner chains)
    float e0 = __expf(-ax0), e1 = __expf(-ax1);
    float m0 = fmaxf(ax0, 3.75f), m1 = fmaxf(ax1, 3.75f);
    float rs0 = rsqrtf(m0), rs1 = rsqrtf(m1);

    uint64_t ax = pk2(ax0, ax1);

    // ---- small branch: ax * P7((ax/3.75)^2) * exp(-ax) ----
    uint64_t ts = mul2(ax, bc2(1.0f / 3.75f));
    ts = mul2(ts, ts);
    uint64_t ps = bc2(0.00032411f);
    ps = fma2(ps, ts, bc2(0.00301532f));
    ps = fma2(ps, ts, bc2(0.02658733f));
    ps = fma2(ps, ts, bc2(0.15084934f));
    ps = fma2(ps, ts, bc2(0.51498869f));
    ps = fma2(ps, ts, bc2(0.87890594f));
    ps = fma2(ps, ts, bc2(0.5f));
    uint64_t sm = mul2(mul2(ax, ps), pk2(e0, e1));

    // ---- large branch: P9(3.75/ax) * rsqrt(ax);  3.75/ax == 3.75*rs*rs ----
    uint64_t rv = pk2(rs0, rs1);
    uint64_t tl = mul2(mul2(rv, rv), bc2(3.75f));
    uint64_t pl = bc2(-0.00420059f);
    pl = fma2(pl, tl, bc2(0.01787654f));
    pl = fma2(pl, tl, bc2(-0.02895312f));
    pl = fma2(pl, tl, bc2(0.02282967f));
    pl = fma2(pl, tl, bc2(-0.01031555f));
    pl = fma2(pl, tl, bc2(0.00163801f));
    pl = fma2(pl, tl, bc2(-0.00362018f));
    pl = fma2(pl, tl, bc2(-0.03988024f));
    pl = fma2(pl, tl, bc2(0.39894228f));
    uint64_t lg = mul2(pl, rv);

    float s0, s1, l0, l1;
    upk2(sm, s0, s1);
    upk2(lg, l0, l1);
    float r0 = (ax0 <= 3.75f) ? s0 : l0;
    float r1 = (ax1 <= 3.75f) ? s1 : l1;
    o0 = copysignf(r0, x0);
    o1 = copysignf(r1, x1);
}

__global__ void __launch_bounds__(256) i1e_vec4_kernel(
    const float4* __restrict__ in, float4* __restrict__ out, int n4) {
    int i = blockIdx.x * blockDim.x + threadIdx.x;
    if (i < n4) {
        float4 v = in[i];
        float4 r;
        i1e_pair(v.x, v.y, r.x, r.y);
        i1e_pair(v.z, v.w, r.z, r.w);
        out[i] = r;
    }
}

__device__ __forceinline__ float i1e_scalar(float x) {
    float o0, o1;
    i1e_pair(x, x, o0, o1);
    return o0;
}

__global__ void i1e_tail_kernel(const float* __restrict__ in,
                                float* __restrict__ out, int start, int n) {
    int i = start + blockIdx.x * blockDim.x + threadIdx.x;
    if (i < n) out[i] = i1e_scalar(in[i]);
}

extern "C" void kernel_launch(void* const* d_in, const int* in_sizes, int n_in,
                              void* d_out, int out_size) {
    const float* z = (const float*)d_in[0];
    float* out = (float*)d_out;
    int n = in_sizes[0];
    int n4 = n >> 2;

    if (n4 > 0) {
        int threads = 256;
        int blocks = (n4 + threads - 1) / threads;
        i1e_vec4_kernel<<<blocks, threads>>>((const float4*)z, (float4*)out, n4);
    }
    int rem_start = n4 << 2;
    int rem = n - rem_start;
    if (rem > 0) {
        i1e_tail_kernel<<<1, 256>>>(z, out, rem_start, n);
    }
}

// round 3
// speedup vs baseline: 1.2619x; 1.0642x over previous
#include <cuda_runtime.h>
#include <cstdint>

// i1e(x) = exp(-|x|) * I1(x), A&S 9.8.3/9.8.4, matching the JAX reference.
// Packed f32x2 math (Blackwell FFMA2); 2 independent float4 loads per thread
// batched up front to double memory-level parallelism.

__device__ __forceinline__ uint64_t pk2(float a, float b) {
    uint64_t r;
    asm("mov.b64 %0, {%1, %2};" : "=l"(r) : "f"(a), "f"(b));
    return r;
}
__device__ __forceinline__ void upk2(uint64_t v, float& a, float& b) {
    asm("mov.b64 {%0, %1}, %2;" : "=f"(a), "=f"(b) : "l"(v));
}
__device__ __forceinline__ uint64_t bc2(float c) {
    uint32_t u = __float_as_uint(c);
    return ((uint64_t)u << 32) | (uint64_t)u;
}
__device__ __forceinline__ uint64_t fma2(uint64_t a, uint64_t b, uint64_t c) {
    uint64_t r;
    asm("fma.rn.f32x2 %0, %1, %2, %3;" : "=l"(r) : "l"(a), "l"(b), "l"(c));
    return r;
}
__device__ __forceinline__ uint64_t mul2(uint64_t a, uint64_t b) {
    uint64_t r;
    asm("mul.rn.f32x2 %0, %1, %2;" : "=l"(r) : "l"(a), "l"(b));
    return r;
}

__device__ __forceinline__ void i1e_pair(float x0, float x1, float& o0, float& o1) {
    float ax0 = fabsf(x0), ax1 = fabsf(x1);

    // MUFU work issued early (long latency, overlaps the packed Horner chains)
    float e0 = __expf(-ax0), e1 = __expf(-ax1);
    float m0 = fmaxf(ax0, 3.75f), m1 = fmaxf(ax1, 3.75f);
    float rs0 = rsqrtf(m0), rs1 = rsqrtf(m1);

    uint64_t ax = pk2(ax0, ax1);

    // small branch: ax * P7((ax/3.75)^2) * exp(-ax)
    uint64_t ts = mul2(ax, bc2(1.0f / 3.75f));
    ts = mul2(ts, ts);
    uint64_t ps = bc2(0.00032411f);
    ps = fma2(ps, ts, bc2(0.00301532f));
    ps = fma2(ps, ts, bc2(0.02658733f));
    ps = fma2(ps, ts, bc2(0.15084934f));
    ps = fma2(ps, ts, bc2(0.51498869f));
    ps = fma2(ps, ts, bc2(0.87890594f));
    ps = fma2(ps, ts, bc2(0.5f));
    uint64_t sm = mul2(mul2(ax, ps), pk2(e0, e1));

    // large branch: P9(3.75/ax) * rsqrt(ax);  3.75/ax == 3.75*rs*rs
    uint64_t rv = pk2(rs0, rs1);
    uint64_t tl = mul2(mul2(rv, rv), bc2(3.75f));
    uint64_t pl = bc2(-0.00420059f);
    pl = fma2(pl, tl, bc2(0.01787654f));
    pl = fma2(pl, tl, bc2(-0.02895312f));
    pl = fma2(pl, tl, bc2(0.02282967f));
    pl = fma2(pl, tl, bc2(-0.01031555f));
    pl = fma2(pl, tl, bc2(0.00163801f));
    pl = fma2(pl, tl, bc2(-0.00362018f));
    pl = fma2(pl, tl, bc2(-0.03988024f));
    pl = fma2(pl, tl, bc2(0.39894228f));
    uint64_t lg = mul2(pl, rv);

    float s0, s1, l0, l1;
    upk2(sm, s0, s1);
    upk2(lg, l0, l1);
    float r0 = (ax0 <= 3.75f) ? s0 : l0;
    float r1 = (ax1 <= 3.75f) ? s1 : l1;
    o0 = copysignf(r0, x0);
    o1 = copysignf(r1, x1);
}

__device__ __forceinline__ float4 i1e_vec(float4 v) {
    float4 r;
    i1e_pair(v.x, v.y, r.x, r.y);
    i1e_pair(v.z, v.w, r.z, r.w);
    return r;
}

// Each thread handles 2 float4s, loads batched front-to-back for MLP=2.
__global__ void __launch_bounds__(256) i1e_vec4x2_kernel(
    const float4* __restrict__ in, float4* __restrict__ out, int half) {
    int i = blockIdx.x * blockDim.x + threadIdx.x;
    if (i < half) {
        float4 a = in[i];
        float4 b = in[i + half];
        float4 ra = i1e_vec(a);
        float4 rb = i1e_vec(b);
        out[i] = ra;
        out[i + half] = rb;
    }
}

__global__ void __launch_bounds__(256) i1e_vec4_kernel(
    const float4* __restrict__ in, float4* __restrict__ out, int lo, int n4) {
    int i = lo + blockIdx.x * blockDim.x + threadIdx.x;
    if (i < n4) out[i] = i1e_vec(in[i]);
}

__device__ __forceinline__ float i1e_scalar(float x) {
    float o0, o1;
    i1e_pair(x, x, o0, o1);
    return o0;
}

__global__ void i1e_tail_kernel(const float* __restrict__ in,
                                float* __restrict__ out, int start, int n) {
    int i = start + blockIdx.x * blockDim.x + threadIdx.x;
    if (i < n) out[i] = i1e_scalar(in[i]);
}

extern "C" void kernel_launch(void* const* d_in, const int* in_sizes, int n_in,
                              void* d_out, int out_size) {
    const float* z = (const float*)d_in[0];
    float* out = (float*)d_out;
    int n = in_sizes[0];
    int n4 = n >> 2;       // number of full float4s
    int half = n4 >> 1;    // threads in the main 2x kernel

    if (half > 0) {
        int threads = 256;
        int blocks = (half + threads - 1) / threads;
        i1e_vec4x2_kernel<<<blocks, threads>>>((const float4*)z, (float4*)out, half);
    }
    // odd leftover float4 (if n4 is odd)
    if (n4 > 2 * half) {
        i1e_vec4_kernel<<<1, 256>>>((const float4*)z, (float4*)out, 2 * half, n4);
    }
    // scalar tail (n not divisible by 4)
    int rem_start = n4 << 2;
    if (n > rem_start) {
        i1e_tail_kernel<<<1, 256>>>(z, out, rem_start, n);
    }
}